// round 4
// baseline (speedup 1.0000x reference)
#include <cuda_runtime.h>
#include <math.h>

#define Bv 8
#define Lv 2048
#define Dv 64
#define BM 16          // query rows per CTA (= #warps)
#define BK 128         // k-tile
#define NT 512         // 16 warps
#define SCALE 0.125f   // 1/sqrt(64)
#define SROW 2052      // padded S row stride (floats), multiple of 4
#define CT1S 132       // phase-1 transposed C-tile row stride (floats), multiple of 4
#define CTBUF (Dv*CT1S)  // one C-tile buffer: 8448 floats (phase2 uses 8192 of it)

// smem floats: S 16*2052 + Qt 1024 + Ct 2*8448  = 50752 floats = 203,008 B
#define SMEM_FLOATS (BM*SROW + BM*Dv + 2*CTBUF)

__global__ __launch_bounds__(NT, 1)
void attn_fused_kernel(const float* __restrict__ Q,
                       const float* __restrict__ C,
                       const unsigned char* __restrict__ M,
                       float* __restrict__ out,
                       float* __restrict__ att)
{
    extern __shared__ float sm[];
    float* S  = sm;                  // [BM][SROW]
    float* Qt = S + BM*SROW;         // [BM][Dv]
    float* Ct = Qt + BM*Dv;          // 2 buffers

    const int t    = threadIdx.x;
    const int lane = t & 31;
    const int w    = t >> 5;         // warp id == row within CTA tile (0..15)
    const int b    = blockIdx.y;
    const int q0   = blockIdx.x * BM;

    const float* Qg = Q + (size_t)(b*Lv + q0) * Dv;
    const float* Cg = C + (size_t)b * Lv * Dv;
    const unsigned char* Mg = M + (size_t)(b*Lv + q0) * Lv;

    // ---- load Q tile (coalesced float4) ----
    if (t < BM*Dv/4) ((float4*)Qt)[t] = ((const float4*)Qg)[t];

    // ---- preload phase-1 tile 0, transposed: Ct[d][k] = Ctile[k][d] ----
    const int d_tr  = t & 63;        // column (d) this thread writes
    const int k0_tr = t >> 6;        // base k, +8j
    float r[16];
    #pragma unroll
    for (int j = 0; j < 16; ++j) r[j] = Cg[t + 512*j];
    #pragma unroll
    for (int j = 0; j < 16; ++j) Ct[d_tr*CT1S + k0_tr + 8*j] = r[j];
    __syncthreads();

    // ================= Phase 1: S = Q @ C^T * scale (masked) =================
    // thread: row = w, cols = 4*lane .. 4*lane+3 within each k-tile
    const float4* Qt4 = (const float4*)(Qt + w*Dv);   // 16 float4, uniform per warp
    #pragma unroll 1
    for (int kt = 0; kt < Lv/BK; ++kt) {
        const float* buf = Ct + (kt & 1) * CTBUF;
        if (kt < Lv/BK - 1) {
            const float* src = Cg + (size_t)(kt+1)*BK*Dv;
            #pragma unroll
            for (int j = 0; j < 16; ++j) r[j] = src[t + 512*j];
        }

        float4 acc = {0.f, 0.f, 0.f, 0.f};
        const float4* B4 = (const float4*)buf;        // row stride 33 float4
        #pragma unroll
        for (int dd = 0; dd < 16; ++dd) {
            const float4 q4 = Qt4[dd];                 // broadcast LDS.128
            float4 c;
            c = B4[(4*dd+0)*33 + lane];
            acc.x = fmaf(q4.x, c.x, acc.x); acc.y = fmaf(q4.x, c.y, acc.y);
            acc.z = fmaf(q4.x, c.z, acc.z); acc.w = fmaf(q4.x, c.w, acc.w);
            c = B4[(4*dd+1)*33 + lane];
            acc.x = fmaf(q4.y, c.x, acc.x); acc.y = fmaf(q4.y, c.y, acc.y);
            acc.z = fmaf(q4.y, c.z, acc.z); acc.w = fmaf(q4.y, c.w, acc.w);
            c = B4[(4*dd+2)*33 + lane];
            acc.x = fmaf(q4.z, c.x, acc.x); acc.y = fmaf(q4.z, c.y, acc.y);
            acc.z = fmaf(q4.z, c.z, acc.z); acc.w = fmaf(q4.z, c.w, acc.w);
            c = B4[(4*dd+3)*33 + lane];
            acc.x = fmaf(q4.w, c.x, acc.x); acc.y = fmaf(q4.w, c.y, acc.y);
            acc.z = fmaf(q4.w, c.z, acc.z); acc.w = fmaf(q4.w, c.w, acc.w);
        }

        if (kt < Lv/BK - 1) {
            float* nbuf = Ct + ((kt+1) & 1) * CTBUF;
            #pragma unroll
            for (int j = 0; j < 16; ++j) nbuf[d_tr*CT1S + k0_tr + 8*j] = r[j];
        }

        // mask + store scores to S (warp-local row)
        const uchar4 mk = ((const uchar4*)(Mg + (size_t)w*Lv + kt*BK))[lane];
        float4 v;
        v.x = acc.x * SCALE; v.y = acc.y * SCALE;
        v.z = acc.z * SCALE; v.w = acc.w * SCALE;
        if (mk.x) v.x = -INFINITY;
        if (mk.y) v.y = -INFINITY;
        if (mk.z) v.z = -INFINITY;
        if (mk.w) v.w = -INFINITY;
        ((float4*)(S + w*SROW + kt*BK))[lane] = v;
        __syncthreads();   // Ct buffer handoff
    }

    // ================= Softmax: warp w owns row w, pure shuffles =============
    float4* Sr = (float4*)(S + w*SROW);   // 512 float4 per row
    float mx = -INFINITY;
    #pragma unroll
    for (int i = 0; i < 16; ++i) {
        float4 v = Sr[lane + 32*i];
        mx = fmaxf(mx, fmaxf(fmaxf(v.x, v.y), fmaxf(v.z, v.w)));
    }
    #pragma unroll
    for (int o = 16; o; o >>= 1) mx = fmaxf(mx, __shfl_xor_sync(0xffffffffu, mx, o));

    float sum = 0.f;
    #pragma unroll
    for (int i = 0; i < 16; ++i) {
        float4 v = Sr[lane + 32*i];
        v.x = __expf(v.x - mx); v.y = __expf(v.y - mx);
        v.z = __expf(v.z - mx); v.w = __expf(v.w - mx);
        Sr[lane + 32*i] = v;                 // S holds unnormalized e
        sum += (v.x + v.y) + (v.z + v.w);
    }
    #pragma unroll
    for (int o = 16; o; o >>= 1) sum += __shfl_xor_sync(0xffffffffu, sum, o);
    const float inv = 1.0f / sum;
    __syncwarp();

    // ---- prefetch phase-2 tile 0 (natural layout) while writing att ----
    float4 p4[4];
    #pragma unroll
    for (int j = 0; j < 4; ++j) p4[j] = ((const float4*)Cg)[t + 512*j];

    float4* attr = (float4*)(att + (size_t)(b*Lv + q0 + w) * Lv);
    #pragma unroll
    for (int i = 0; i < 16; ++i) {
        float4 v = Sr[lane + 32*i];
        v.x *= inv; v.y *= inv; v.z *= inv; v.w *= inv;
        attr[lane + 32*i] = v;               // coalesced normalized att
    }

    // phase-1 Ct reads all ended at the kt=15 barrier; safe to overwrite now
    #pragma unroll
    for (int j = 0; j < 4; ++j) ((float4*)Ct)[t + 512*j] = p4[j];
    __syncthreads();

    // ================= Phase 2: out = (e @ C) * inv ==========================
    // thread: row = w, cols = 2*lane, 2*lane+1
    float2 acc2 = {0.f, 0.f};
    const float* Srow = S + w*SROW;
    #pragma unroll 1
    for (int kt = 0; kt < Lv/BK; ++kt) {
        const float* buf = Ct + (kt & 1) * CTBUF;
        if (kt < Lv/BK - 1) {
            const float4* src = (const float4*)(Cg + (size_t)(kt+1)*BK*Dv);
            #pragma unroll
            for (int j = 0; j < 4; ++j) p4[j] = src[t + 512*j];
        }

        const float2* B2 = (const float2*)buf;             // [128][32] float2
        const float4* S4r = (const float4*)(Srow + kt*BK); // uniform per warp
        #pragma unroll 8
        for (int kk = 0; kk < 32; ++kk) {
            const float4 s4 = S4r[kk];                     // broadcast LDS.128
            float2 c;
            c = B2[(4*kk+0)*32 + lane];
            acc2.x = fmaf(s4.x, c.x, acc2.x); acc2.y = fmaf(s4.x, c.y, acc2.y);
            c = B2[(4*kk+1)*32 + lane];
            acc2.x = fmaf(s4.y, c.x, acc2.x); acc2.y = fmaf(s4.y, c.y, acc2.y);
            c = B2[(4*kk+2)*32 + lane];
            acc2.x = fmaf(s4.z, c.x, acc2.x); acc2.y = fmaf(s4.z, c.y, acc2.y);
            c = B2[(4*kk+3)*32 + lane];
            acc2.x = fmaf(s4.w, c.x, acc2.x); acc2.y = fmaf(s4.w, c.y, acc2.y);
        }

        if (kt < Lv/BK - 1) {
            float4* nbuf = (float4*)(Ct + ((kt+1) & 1) * CTBUF);
            #pragma unroll
            for (int j = 0; j < 4; ++j) nbuf[t + 512*j] = p4[j];
        }
        __syncthreads();
    }

    float2 o2;
    o2.x = acc2.x * inv;
    o2.y = acc2.y * inv;
    ((float2*)(out + (size_t)(b*Lv + q0 + w) * Dv))[lane] = o2;
}

extern "C" void kernel_launch(void* const* d_in, const int* in_sizes, int n_in,
                              void* d_out, int out_size) {
    const float* Q = (const float*)d_in[0];
    const float* C = (const float*)d_in[1];
    const unsigned char* M = (const unsigned char*)d_in[2];

    float* out = (float*)d_out;                   // [B, L, D]
    float* att = out + (size_t)Bv * Lv * Dv;      // [B, L, L]

    const size_t smem_bytes = (size_t)SMEM_FLOATS * sizeof(float);  // ~203 KB
    cudaFuncSetAttribute(attn_fused_kernel,
                         cudaFuncAttributeMaxDynamicSharedMemorySize,
                         (int)smem_bytes);

    dim3 grid(Lv / BM, Bv);
    attn_fused_kernel<<<grid, NT, smem_bytes>>>(Q, C, M, out, att);
}

// round 5
// speedup vs baseline: 1.0527x; 1.0527x over previous
#include <cuda_runtime.h>
#include <math.h>

#define Bv 8
#define Lv 2048
#define Dv 64
#define BM 16          // query rows per CTA (= #warps)
#define BK 128         // k-tile
#define NT 512         // 16 warps
#define SCALE 0.125f   // 1/sqrt(64)
#define SROW 2052      // padded S row stride (floats), multiple of 4
#define CT1S 132       // phase-1 transposed C-tile row stride (floats), multiple of 4
#define CTBUF (Dv*CT1S)  // one C-tile buffer: 8448 floats (phase2 uses 8192 of it)

// smem floats: S 16*2052 + Qt 1024 + Ct 2*8448  = 50752 floats = 203,008 B
#define SMEM_FLOATS (BM*SROW + BM*Dv + 2*CTBUF)

__global__ __launch_bounds__(NT, 1)
void attn_fused_kernel(const float* __restrict__ Q,
                       const float* __restrict__ C,
                       const unsigned char* __restrict__ M,
                       float* __restrict__ out,
                       float* __restrict__ att)
{
    extern __shared__ float sm[];
    float* S  = sm;                  // [BM][SROW]
    float* Qt = S + BM*SROW;         // [BM][Dv]
    float* Ct = Qt + BM*Dv;          // 2 buffers

    const int t    = threadIdx.x;
    const int lane = t & 31;
    const int w    = t >> 5;         // warp id == row within CTA tile (0..15)
    const int b    = blockIdx.y;
    const int q0   = blockIdx.x * BM;

    const float* Qg = Q + (size_t)(b*Lv + q0) * Dv;
    const float* Cg = C + (size_t)b * Lv * Dv;
    const unsigned char* Mg = M + (size_t)(b*Lv + q0) * Lv;

    // ---- load Q tile (coalesced float4) ----
    if (t < BM*Dv/4) ((float4*)Qt)[t] = ((const float4*)Qg)[t];

    // ---- preload phase-1 tile 0, transposed: Ct[d][k] = Ctile[k][d] ----
    const int d_tr  = t & 63;        // column (d) this thread writes
    const int k0_tr = t >> 6;        // base k, +8j
    float r[16];
    #pragma unroll
    for (int j = 0; j < 16; ++j) r[j] = Cg[t + 512*j];
    #pragma unroll
    for (int j = 0; j < 16; ++j) Ct[d_tr*CT1S + k0_tr + 8*j] = r[j];
    __syncthreads();

    // ================= Phase 1: S = Q @ C^T * scale (masked) =================
    // thread: row = w, cols = 4*lane .. 4*lane+3 within each k-tile
    const float4* Qt4 = (const float4*)(Qt + w*Dv);   // 16 float4, uniform per warp
    #pragma unroll 1
    for (int kt = 0; kt < Lv/BK; ++kt) {
        const float* buf = Ct + (kt & 1) * CTBUF;
        if (kt < Lv/BK - 1) {
            const float* src = Cg + (size_t)(kt+1)*BK*Dv;
            #pragma unroll
            for (int j = 0; j < 16; ++j) r[j] = src[t + 512*j];
        }

        float4 acc = {0.f, 0.f, 0.f, 0.f};
        const float4* B4 = (const float4*)buf;        // row stride 33 float4
        #pragma unroll
        for (int dd = 0; dd < 16; ++dd) {
            const float4 q4 = Qt4[dd];                 // broadcast LDS.128
            float4 c;
            c = B4[(4*dd+0)*33 + lane];
            acc.x = fmaf(q4.x, c.x, acc.x); acc.y = fmaf(q4.x, c.y, acc.y);
            acc.z = fmaf(q4.x, c.z, acc.z); acc.w = fmaf(q4.x, c.w, acc.w);
            c = B4[(4*dd+1)*33 + lane];
            acc.x = fmaf(q4.y, c.x, acc.x); acc.y = fmaf(q4.y, c.y, acc.y);
            acc.z = fmaf(q4.y, c.z, acc.z); acc.w = fmaf(q4.y, c.w, acc.w);
            c = B4[(4*dd+2)*33 + lane];
            acc.x = fmaf(q4.z, c.x, acc.x); acc.y = fmaf(q4.z, c.y, acc.y);
            acc.z = fmaf(q4.z, c.z, acc.z); acc.w = fmaf(q4.z, c.w, acc.w);
            c = B4[(4*dd+3)*33 + lane];
            acc.x = fmaf(q4.w, c.x, acc.x); acc.y = fmaf(q4.w, c.y, acc.y);
            acc.z = fmaf(q4.w, c.z, acc.z); acc.w = fmaf(q4.w, c.w, acc.w);
        }

        if (kt < Lv/BK - 1) {
            float* nbuf = Ct + ((kt+1) & 1) * CTBUF;
            #pragma unroll
            for (int j = 0; j < 16; ++j) nbuf[d_tr*CT1S + k0_tr + 8*j] = r[j];
        }

        // mask + store scores to S (warp-local row)
        const uchar4 mk = ((const uchar4*)(Mg + (size_t)w*Lv + kt*BK))[lane];
        float4 v;
        v.x = acc.x * SCALE; v.y = acc.y * SCALE;
        v.z = acc.z * SCALE; v.w = acc.w * SCALE;
        if (mk.x) v.x = -INFINITY;
        if (mk.y) v.y = -INFINITY;
        if (mk.z) v.z = -INFINITY;
        if (mk.w) v.w = -INFINITY;
        ((float4*)(S + w*SROW + kt*BK))[lane] = v;
        __syncthreads();   // Ct buffer handoff
    }

    // ================= Softmax: warp w owns row w, pure shuffles =============
    float4* Sr = (float4*)(S + w*SROW);   // 512 float4 per row
    float mx = -INFINITY;
    #pragma unroll
    for (int i = 0; i < 16; ++i) {
        float4 v = Sr[lane + 32*i];
        mx = fmaxf(mx, fmaxf(fmaxf(v.x, v.y), fmaxf(v.z, v.w)));
    }
    #pragma unroll
    for (int o = 16; o; o >>= 1) mx = fmaxf(mx, __shfl_xor_sync(0xffffffffu, mx, o));

    float sum = 0.f;
    #pragma unroll
    for (int i = 0; i < 16; ++i) {
        float4 v = Sr[lane + 32*i];
        v.x = __expf(v.x - mx); v.y = __expf(v.y - mx);
        v.z = __expf(v.z - mx); v.w = __expf(v.w - mx);
        Sr[lane + 32*i] = v;                 // S holds unnormalized e
        sum += (v.x + v.y) + (v.z + v.w);
    }
    #pragma unroll
    for (int o = 16; o; o >>= 1) sum += __shfl_xor_sync(0xffffffffu, sum, o);
    const float inv = 1.0f / sum;
    __syncwarp();

    // ---- prefetch phase-2 tile 0 (natural layout) while writing att ----
    float4 p4[4];
    #pragma unroll
    for (int j = 0; j < 4; ++j) p4[j] = ((const float4*)Cg)[t + 512*j];

    float4* attr = (float4*)(att + (size_t)(b*Lv + q0 + w) * Lv);
    #pragma unroll
    for (int i = 0; i < 16; ++i) {
        float4 v = Sr[lane + 32*i];
        v.x *= inv; v.y *= inv; v.z *= inv; v.w *= inv;
        attr[lane + 32*i] = v;               // coalesced normalized att
    }

    // phase-1 Ct reads all ended at the kt=15 barrier; safe to overwrite now
    #pragma unroll
    for (int j = 0; j < 4; ++j) ((float4*)Ct)[t + 512*j] = p4[j];
    __syncthreads();

    // ================= Phase 2: out = (e @ C) * inv ==========================
    // thread: row = w, cols = 2*lane, 2*lane+1
    float2 acc2 = {0.f, 0.f};
    const float* Srow = S + w*SROW;
    #pragma unroll 1
    for (int kt = 0; kt < Lv/BK; ++kt) {
        const float* buf = Ct + (kt & 1) * CTBUF;
        if (kt < Lv/BK - 1) {
            const float4* src = (const float4*)(Cg + (size_t)(kt+1)*BK*Dv);
            #pragma unroll
            for (int j = 0; j < 4; ++j) p4[j] = src[t + 512*j];
        }

        const float2* B2 = (const float2*)buf;             // [128][32] float2
        const float4* S4r = (const float4*)(Srow + kt*BK); // uniform per warp
        #pragma unroll 8
        for (int kk = 0; kk < 32; ++kk) {
            const float4 s4 = S4r[kk];                     // broadcast LDS.128
            float2 c;
            c = B2[(4*kk+0)*32 + lane];
            acc2.x = fmaf(s4.x, c.x, acc2.x); acc2.y = fmaf(s4.x, c.y, acc2.y);
            c = B2[(4*kk+1)*32 + lane];
            acc2.x = fmaf(s4.y, c.x, acc2.x); acc2.y = fmaf(s4.y, c.y, acc2.y);
            c = B2[(4*kk+2)*32 + lane];
            acc2.x = fmaf(s4.z, c.x, acc2.x); acc2.y = fmaf(s4.z, c.y, acc2.y);
            c = B2[(4*kk+3)*32 + lane];
            acc2.x = fmaf(s4.w, c.x, acc2.x); acc2.y = fmaf(s4.w, c.y, acc2.y);
        }

        if (kt < Lv/BK - 1) {
            float4* nbuf = (float4*)(Ct + ((kt+1) & 1) * CTBUF);
            #pragma unroll
            for (int j = 0; j < 4; ++j) nbuf[t + 512*j] = p4[j];
        }
        __syncthreads();
    }

    float2 o2;
    o2.x = acc2.x * inv;
    o2.y = acc2.y * inv;
    ((float2*)(out + (size_t)(b*Lv + q0 + w) * Dv))[lane] = o2;
}

extern "C" void kernel_launch(void* const* d_in, const int* in_sizes, int n_in,
                              void* d_out, int out_size) {
    const float* Q = (const float*)d_in[0];
    const float* C = (const float*)d_in[1];
    const unsigned char* M = (const unsigned char*)d_in[2];

    float* out = (float*)d_out;                   // [B, L, D]
    float* att = out + (size_t)Bv * Lv * Dv;      // [B, L, L]

    const size_t smem_bytes = (size_t)SMEM_FLOATS * sizeof(float);  // ~203 KB
    cudaFuncSetAttribute(attn_fused_kernel,
                         cudaFuncAttributeMaxDynamicSharedMemorySize,
                         (int)smem_bytes);

    dim3 grid(Lv / BM, Bv);
    attn_fused_kernel<<<grid, NT, smem_bytes>>>(Q, C, M, out, att);
}

// round 6
// speedup vs baseline: 1.6159x; 1.5350x over previous
#include <cuda_runtime.h>
#include <math.h>

#define Bv 8
#define Lv 2048
#define Dv 64
#define BM 16          // query rows per CTA
#define BK 128         // k-tile
#define NT 512         // 16 warps
#define SCALE 0.125f   // 1/sqrt(64)
#define SROW 2052      // padded S row stride (floats), multiple of 4
#define CT1S 132       // phase-1 transposed C-tile row stride (floats)
#define CTBUF (Dv*CT1S)  // one C-tile buffer: 8448 floats
#define QTRS 20        // Qtr row stride (floats), multiple of 4, conflict-light

// smem floats: S 16*2052=32832 + Qtr 64*20=1280 + Ct 2*8448=16896 + rinvs 16
#define SMEM_FLOATS (BM*SROW + Dv*QTRS + 2*CTBUF + 16)

__global__ __launch_bounds__(NT, 1)
void attn_fused_kernel(const float* __restrict__ Q,
                       const float* __restrict__ C,
                       const unsigned char* __restrict__ M,
                       float* __restrict__ out,
                       float* __restrict__ att)
{
    extern __shared__ float sm[];
    float* S     = sm;                   // [BM][SROW]
    float* Qtr   = S + BM*SROW;          // [Dv][QTRS] transposed Q: Qtr[d][row]
    float* Ct    = Qtr + Dv*QTRS;        // 2 C-tile buffers
    float* rinvs = Ct + 2*CTBUF;         // [BM]

    const int t    = threadIdx.x;
    const int lane = t & 31;
    const int w    = t >> 5;             // warp id
    const int b    = blockIdx.y;
    const int q0   = blockIdx.x * BM;

    const float* Qg = Q + (size_t)(b*Lv + q0) * Dv;
    const float* Cg = C + (size_t)b * Lv * Dv;
    const unsigned char* Mg = M + (size_t)(b*Lv + q0) * Lv;

    // ---- load Q tile transposed: Qtr[d][row] ----
    #pragma unroll
    for (int i = t; i < BM*Dv; i += NT) {
        int row = i >> 6, d = i & 63;
        Qtr[d*QTRS + row] = Qg[i];
    }

    // ---- preload phase-1 tile 0, transposed: Ct[d][k] ----
    const int d_tr  = t & 63;
    const int k0_tr = t >> 6;
    float r[16];
    #pragma unroll
    for (int j = 0; j < 16; ++j) r[j] = Cg[t + 512*j];
    #pragma unroll
    for (int j = 0; j < 16; ++j) Ct[d_tr*CT1S + k0_tr + 8*j] = r[j];
    __syncthreads();

    // ================= Phase 1: S = Q @ C^T * scale (masked) =================
    // warp: rows 4*rg..4*rg+3, col kg*32+lane within tile
    {
        const int rg = w >> 2;
        const int kg = w & 3;
        const float* qb = Qtr + 4*rg;

        #pragma unroll 1
        for (int kt = 0; kt < Lv/BK; ++kt) {
            const float* buf = Ct + (kt & 1) * CTBUF;
            if (kt < Lv/BK - 1) {
                const float* src = Cg + (size_t)(kt+1)*BK*Dv;
                #pragma unroll
                for (int j = 0; j < 16; ++j) r[j] = src[t + 512*j];
            }

            float acc0 = 0.f, acc1 = 0.f, acc2 = 0.f, acc3 = 0.f;
            const float* cp = buf + kg*32 + lane;
            #pragma unroll
            for (int d = 0; d < Dv; ++d) {
                const float c  = cp[d*CT1S];                     // 1-cyc wavefront
                const float4 q = *(const float4*)(qb + d*QTRS);  // broadcast
                acc0 = fmaf(q.x, c, acc0);
                acc1 = fmaf(q.y, c, acc1);
                acc2 = fmaf(q.z, c, acc2);
                acc3 = fmaf(q.w, c, acc3);
            }

            if (kt < Lv/BK - 1) {
                float* nbuf = Ct + ((kt+1) & 1) * CTBUF;
                #pragma unroll
                for (int j = 0; j < 16; ++j) nbuf[d_tr*CT1S + k0_tr + 8*j] = r[j];
            }

            const int k = kt*BK + kg*32 + lane;
            float a[4] = {acc0, acc1, acc2, acc3};
            #pragma unroll
            for (int j = 0; j < 4; ++j) {
                const int rr = 4*rg + j;
                float v = a[j] * SCALE;
                if (Mg[(size_t)rr*Lv + k]) v = -INFINITY;
                S[rr*SROW + kt*BK + kg*32 + lane] = v;
            }
            __syncthreads();
        }
    }

    // ================= Softmax: warp w owns row w =================
    float inv;
    {
        float4* Sr = (float4*)(S + w*SROW);
        float mx = -INFINITY;
        #pragma unroll
        for (int i = 0; i < 16; ++i) {
            float4 v = Sr[lane + 32*i];
            mx = fmaxf(mx, fmaxf(fmaxf(v.x, v.y), fmaxf(v.z, v.w)));
        }
        #pragma unroll
        for (int o = 16; o; o >>= 1) mx = fmaxf(mx, __shfl_xor_sync(0xffffffffu, mx, o));

        float sum = 0.f;
        #pragma unroll
        for (int i = 0; i < 16; ++i) {
            float4 v = Sr[lane + 32*i];
            v.x = __expf(v.x - mx); v.y = __expf(v.y - mx);
            v.z = __expf(v.z - mx); v.w = __expf(v.w - mx);
            Sr[lane + 32*i] = v;             // S holds unnormalized e
            sum += (v.x + v.y) + (v.z + v.w);
        }
        #pragma unroll
        for (int o = 16; o; o >>= 1) sum += __shfl_xor_sync(0xffffffffu, sum, o);
        inv = 1.0f / sum;
        if (lane == 0) rinvs[w] = inv;
    }
    __syncwarp();

    // ---- prefetch phase-2 tile 0 (natural layout) while writing att ----
    float4 p4[4];
    #pragma unroll
    for (int j = 0; j < 4; ++j) p4[j] = ((const float4*)Cg)[t + 512*j];

    {
        float4* Sr = (float4*)(S + w*SROW);
        float4* attr = (float4*)(att + (size_t)(b*Lv + q0 + w) * Lv);
        #pragma unroll
        for (int i = 0; i < 16; ++i) {
            float4 v = Sr[lane + 32*i];
            v.x *= inv; v.y *= inv; v.z *= inv; v.w *= inv;
            attr[lane + 32*i] = v;           // coalesced normalized att
        }
    }

    #pragma unroll
    for (int j = 0; j < 4; ++j) ((float4*)Ct)[t + 512*j] = p4[j];
    __syncthreads();

    // ================= Phase 2: out = (e @ C) * inv =================
    // warp: rows 4*rg..4*rg+3, cols 2*lane..2*lane+1, k-quadrant ks (32 k's per tile)
    {
        const int rg = w >> 2;
        const int ks = w & 3;
        float2 a0 = {0,0}, a1 = {0,0}, a2 = {0,0}, a3 = {0,0};
        const float* S0 = S + (4*rg+0)*SROW;
        const float* S1 = S + (4*rg+1)*SROW;
        const float* S2 = S + (4*rg+2)*SROW;
        const float* S3 = S + (4*rg+3)*SROW;

        #pragma unroll 1
        for (int kt = 0; kt < Lv/BK; ++kt) {
            const float* buf = Ct + (kt & 1) * CTBUF;
            if (kt < Lv/BK - 1) {
                const float4* src = (const float4*)(Cg + (size_t)(kt+1)*BK*Dv);
                #pragma unroll
                for (int j = 0; j < 4; ++j) p4[j] = src[t + 512*j];
            }

            const float2* B2 = (const float2*)buf + ks*32*32;   // k-local base
            const int so = kt*BK + ks*32;
            #pragma unroll
            for (int kk = 0; kk < 8; ++kk) {
                const float4 s0 = *(const float4*)(S0 + so + kk*4);  // broadcasts
                const float4 s1 = *(const float4*)(S1 + so + kk*4);
                const float4 s2 = *(const float4*)(S2 + so + kk*4);
                const float4 s3 = *(const float4*)(S3 + so + kk*4);
                float2 c;
                c = B2[(kk*4+0)*32 + lane];
                a0.x=fmaf(s0.x,c.x,a0.x); a0.y=fmaf(s0.x,c.y,a0.y);
                a1.x=fmaf(s1.x,c.x,a1.x); a1.y=fmaf(s1.x,c.y,a1.y);
                a2.x=fmaf(s2.x,c.x,a2.x); a2.y=fmaf(s2.x,c.y,a2.y);
                a3.x=fmaf(s3.x,c.x,a3.x); a3.y=fmaf(s3.x,c.y,a3.y);
                c = B2[(kk*4+1)*32 + lane];
                a0.x=fmaf(s0.y,c.x,a0.x); a0.y=fmaf(s0.y,c.y,a0.y);
                a1.x=fmaf(s1.y,c.x,a1.x); a1.y=fmaf(s1.y,c.y,a1.y);
                a2.x=fmaf(s2.y,c.x,a2.x); a2.y=fmaf(s2.y,c.y,a2.y);
                a3.x=fmaf(s3.y,c.x,a3.x); a3.y=fmaf(s3.y,c.y,a3.y);
                c = B2[(kk*4+2)*32 + lane];
                a0.x=fmaf(s0.z,c.x,a0.x); a0.y=fmaf(s0.z,c.y,a0.y);
                a1.x=fmaf(s1.z,c.x,a1.x); a1.y=fmaf(s1.z,c.y,a1.y);
                a2.x=fmaf(s2.z,c.x,a2.x); a2.y=fmaf(s2.z,c.y,a2.y);
                a3.x=fmaf(s3.z,c.x,a3.x); a3.y=fmaf(s3.z,c.y,a3.y);
                c = B2[(kk*4+3)*32 + lane];
                a0.x=fmaf(s0.w,c.x,a0.x); a0.y=fmaf(s0.w,c.y,a0.y);
                a1.x=fmaf(s1.w,c.x,a1.x); a1.y=fmaf(s1.w,c.y,a1.y);
                a2.x=fmaf(s2.w,c.x,a2.x); a2.y=fmaf(s2.w,c.y,a2.y);
                a3.x=fmaf(s3.w,c.x,a3.x); a3.y=fmaf(s3.w,c.y,a3.y);
            }

            if (kt < Lv/BK - 1) {
                float4* nbuf = (float4*)(Ct + ((kt+1) & 1) * CTBUF);
                #pragma unroll
                for (int j = 0; j < 4; ++j) nbuf[t + 512*j] = p4[j];
            }
            __syncthreads();
        }

        // ---- cross-warp (ks) reduction of partial out via smem ----
        float* Ored = Ct;   // reuse buffer 0: 4*16*64 = 4096 floats
        ((float2*)(Ored + (ks*16 + 4*rg + 0)*64))[lane] = a0;
        ((float2*)(Ored + (ks*16 + 4*rg + 1)*64))[lane] = a1;
        ((float2*)(Ored + (ks*16 + 4*rg + 2)*64))[lane] = a2;
        ((float2*)(Ored + (ks*16 + 4*rg + 3)*64))[lane] = a3;
        __syncthreads();

        const int row = t >> 5;     // 0..15
        const int c2  = t & 31;     // float2 column
        float2 v0 = ((float2*)(Ored + (0*16 + row)*64))[c2];
        float2 v1 = ((float2*)(Ored + (1*16 + row)*64))[c2];
        float2 v2 = ((float2*)(Ored + (2*16 + row)*64))[c2];
        float2 v3 = ((float2*)(Ored + (3*16 + row)*64))[c2];
        const float rv = rinvs[row];
        float2 o;
        o.x = ((v0.x + v1.x) + (v2.x + v3.x)) * rv;
        o.y = ((v0.y + v1.y) + (v2.y + v3.y)) * rv;
        ((float2*)(out + (size_t)(b*Lv + q0 + row) * Dv))[c2] = o;
    }
}

extern "C" void kernel_launch(void* const* d_in, const int* in_sizes, int n_in,
                              void* d_out, int out_size) {
    const float* Q = (const float*)d_in[0];
    const float* C = (const float*)d_in[1];
    const unsigned char* M = (const unsigned char*)d_in[2];

    float* out = (float*)d_out;                   // [B, L, D]
    float* att = out + (size_t)Bv * Lv * Dv;      // [B, L, L]

    const size_t smem_bytes = (size_t)SMEM_FLOATS * sizeof(float);  // ~204 KB
    cudaFuncSetAttribute(attn_fused_kernel,
                         cudaFuncAttributeMaxDynamicSharedMemorySize,
                         (int)smem_bytes);

    dim3 grid(Lv / BM, Bv);
    attn_fused_kernel<<<grid, NT, smem_bytes>>>(Q, C, M, out, att);
}

// round 7
// speedup vs baseline: 2.0336x; 1.2585x over previous
#include <cuda_runtime.h>
#include <math.h>

#define Bv 8
#define Lv 2048
#define Dv 64
#define BM 16            // query rows per CTA
#define BK 256           // k-tile
#define NTILE (Lv/BK)    // 8
#define NT 512           // 16 warps
#define SCALE 0.125f     // 1/sqrt(64)
#define SROW 2052        // padded S row stride (floats)
#define CT1S 257         // transposed C-tile row stride: odd -> conflict-free STS/LDS
#define QTRS 20          // Qtr row stride (floats), 16B-aligned rows
#define CTSZ (Dv*CT1S)   // 16448 floats (phase-2 natural layout needs 16384)

// smem floats: S 32832 + Qtr 1280 + Ct 16448 + sums 128 + rinvs 16 = 50704 (202.8 KB)
#define SMEM_FLOATS (BM*SROW + Dv*QTRS + CTSZ + 128 + 16)

typedef unsigned long long ull;

#define FMA2(d_, a_, b_, c_) \
    asm("fma.rn.f32x2 %0, %1, %2, %3;" : "=l"(d_) : "l"(a_), "l"(b_), "l"(c_))
#define PACKF2(d_, x_, y_) \
    asm("mov.b64 %0, {%1, %2};" : "=l"(d_) : "f"(x_), "f"(y_))
#define UNPACKF2(x_, y_, s_) \
    asm("mov.b64 {%0, %1}, %2;" : "=f"(x_), "=f"(y_) : "l"(s_))

__global__ __launch_bounds__(NT, 1)
void attn_fused_kernel(const float* __restrict__ Q,
                       const float* __restrict__ C,
                       const unsigned char* __restrict__ M,
                       float* __restrict__ out,
                       float* __restrict__ att)
{
    extern __shared__ float sm[];
    float* S     = sm;                    // [BM][SROW], holds unnormalized e
    float* Qtr   = S + BM*SROW;           // [Dv][QTRS]: Qtr[d][row]
    float* Ct    = Qtr + Dv*QTRS;         // C tile (transposed in ph1, natural in ph2)
    float* sums  = Ct + CTSZ;             // [BM][8] partial row sums
    float* rinvs = sums + 128;            // [BM]

    const int t    = threadIdx.x;
    const int lane = t & 31;
    const int w    = t >> 5;
    const int rg   = w >> 3;              // 0/1: rows 8*rg .. 8*rg+7
    const int kg   = w & 7;               // col-group / k-segment
    const int b    = blockIdx.y;
    const int q0   = blockIdx.x * BM;

    const float* Qg = Q + (size_t)(b*Lv + q0) * Dv;
    const float* Cg = C + (size_t)b * Lv * Dv;
    const unsigned char* Mg = M + (size_t)(b*Lv + q0) * Lv;

    // ---- stage tile 0 transposed (Ct[d][k]) + Q transposed (Qtr[d][row]) ----
    const int d_tr  = t & 63;
    const int k0_tr = t >> 6;             // 0..7, +8j covers k 0..255
    {
        float r0[32];
        #pragma unroll
        for (int j = 0; j < 32; ++j) r0[j] = Cg[t + 512*j];
        #pragma unroll
        for (int j = 0; j < 32; ++j) Ct[d_tr*CT1S + k0_tr + 8*j] = r0[j];
    }
    #pragma unroll
    for (int i = t; i < BM*Dv; i += NT)
        Qtr[(i & 63)*QTRS + (i >> 6)] = Qg[i];
    __syncthreads();

    // ================= Phase 1: e = exp(Q@C^T * scale), fused =================
    float psum[8] = {0.f,0.f,0.f,0.f,0.f,0.f,0.f,0.f};
    {
        float r[32];
        #pragma unroll 1
        for (int kt = 0; kt < NTILE; ++kt) {
            if (kt < NTILE-1) {
                const float* src = Cg + (size_t)(kt+1)*BK*Dv;
                #pragma unroll
                for (int j = 0; j < 32; ++j) r[j] = src[t + 512*j];
            }

            ull a01 = 0, a23 = 0, a45 = 0, a67 = 0;
            const float* cp = Ct + kg*32 + lane;
            const float* qp = Qtr + 8*rg;
            #pragma unroll
            for (int d = 0; d < Dv; ++d) {
                const float c = cp[d*CT1S];              // conflict-free
                ull cc; PACKF2(cc, c, c);
                const ulonglong2 qA = *(const ulonglong2*)(qp + d*QTRS);     // rows 0-3 pairs
                const ulonglong2 qB = *(const ulonglong2*)(qp + d*QTRS + 4); // rows 4-7 pairs
                FMA2(a01, qA.x, cc, a01);
                FMA2(a23, qA.y, cc, a23);
                FMA2(a45, qB.x, cc, a45);
                FMA2(a67, qB.y, cc, a67);
            }

            float s[8];
            UNPACKF2(s[0], s[1], a01);
            UNPACKF2(s[2], s[3], a23);
            UNPACKF2(s[4], s[5], a45);
            UNPACKF2(s[6], s[7], a67);

            const int k = kt*BK + kg*32 + lane;
            #pragma unroll
            for (int j = 0; j < 8; ++j) {
                const int rr = 8*rg + j;
                float e = Mg[(size_t)rr*Lv + k] ? 0.f : __expf(s[j] * SCALE);
                psum[j] += e;
                S[rr*SROW + k] = e;
            }

            if (kt < NTILE-1) {
                __syncthreads();   // all reads of Ct done
                #pragma unroll
                for (int j = 0; j < 32; ++j) Ct[d_tr*CT1S + k0_tr + 8*j] = r[j];
                __syncthreads();   // new tile visible
            }
        }
    }
    __syncthreads();   // S complete

    // ---- row-sum reduction: lane-shuffle then tiny smem combine ----
    #pragma unroll
    for (int j = 0; j < 8; ++j) {
        #pragma unroll
        for (int o = 16; o; o >>= 1)
            psum[j] += __shfl_xor_sync(0xffffffffu, psum[j], o);
    }
    if (lane == 0) {
        #pragma unroll
        for (int j = 0; j < 8; ++j) sums[(8*rg + j)*8 + kg] = psum[j];
    }
    __syncthreads();
    if (t < BM) {
        float ssum = 0.f;
        #pragma unroll
        for (int p = 0; p < 8; ++p) ssum += sums[t*8 + p];
        rinvs[t] = 1.0f / ssum;
    }
    __syncthreads();

    // ---- att write (warp w owns row w) + phase-2 tile-0 prefetch ----
    float4 p4[8];
    #pragma unroll
    for (int j = 0; j < 8; ++j) p4[j] = ((const float4*)Cg)[t + 512*j];

    {
        const float inv = rinvs[w];
        const float4* Sr = (const float4*)(S + w*SROW);
        float4* attr = (float4*)(att + (size_t)(b*Lv + q0 + w) * Lv);
        #pragma unroll
        for (int i = 0; i < 16; ++i) {
            float4 v = Sr[lane + 32*i];
            v.x *= inv; v.y *= inv; v.z *= inv; v.w *= inv;
            attr[lane + 32*i] = v;
        }
    }

    #pragma unroll
    for (int j = 0; j < 8; ++j) ((float4*)Ct)[t + 512*j] = p4[j];   // natural layout
    __syncthreads();

    // ================= Phase 2: out = (e @ C) * inv =================
    // warp (rg, ks=kg): rows 8rg..8rg+7, cols 2lane..2lane+1 (packed), k-seg 32/tile
    ull acc[8] = {0,0,0,0,0,0,0,0};
    #pragma unroll 1
    for (int kt = 0; kt < NTILE; ++kt) {
        if (kt < NTILE-1) {
            const float4* src = (const float4*)(Cg + (size_t)(kt+1)*BK*Dv);
            #pragma unroll
            for (int j = 0; j < 8; ++j) p4[j] = src[t + 512*j];
        }

        const float* Sb = S + 8*rg*SROW + kt*BK + kg*32;
        #pragma unroll
        for (int kk = 0; kk < 8; ++kk) {
            float4 sv[8];
            #pragma unroll
            for (int i = 0; i < 8; ++i)
                sv[i] = *(const float4*)(Sb + i*SROW + kk*4);   // broadcast LDS.128

            #pragma unroll
            for (int q = 0; q < 4; ++q) {
                const ull c = *(const ull*)(Ct + (kg*32 + kk*4 + q)*64 + 2*lane); // packed col-pair
                #pragma unroll
                for (int i = 0; i < 8; ++i) {
                    const float sq = (q == 0) ? sv[i].x : (q == 1) ? sv[i].y
                                   : (q == 2) ? sv[i].z : sv[i].w;
                    ull ss; PACKF2(ss, sq, sq);
                    FMA2(acc[i], ss, c, acc[i]);
                }
            }
        }

        if (kt < NTILE-1) {
            __syncthreads();
            #pragma unroll
            for (int j = 0; j < 8; ++j) ((float4*)Ct)[t + 512*j] = p4[j];
            __syncthreads();
        }
    }
    __syncthreads();   // all warps done reading Ct before reuse

    // ---- cross-ks partial reduction via smem (reuse Ct) ----
    float* Ored = Ct;   // 8 segs * 16 rows * 64 cols = 8192 floats
    #pragma unroll
    for (int i = 0; i < 8; ++i)
        *(ull*)(Ored + (kg*16 + 8*rg + i)*64 + 2*lane) = acc[i];
    __syncthreads();

    const int row = t >> 5;
    float2 o = {0.f, 0.f};
    #pragma unroll
    for (int p = 0; p < 8; ++p) {
        const float2 v = *(const float2*)(Ored + (p*16 + row)*64 + 2*lane);
        o.x += v.x; o.y += v.y;
    }
    const float rv = rinvs[row];
    o.x *= rv; o.y *= rv;
    *(float2*)(out + (size_t)(b*Lv + q0 + row)*Dv + 2*lane) = o;
}

extern "C" void kernel_launch(void* const* d_in, const int* in_sizes, int n_in,
                              void* d_out, int out_size) {
    const float* Q = (const float*)d_in[0];
    const float* C = (const float*)d_in[1];
    const unsigned char* M = (const unsigned char*)d_in[2];

    float* out = (float*)d_out;                   // [B, L, D]
    float* att = out + (size_t)Bv * Lv * Dv;      // [B, L, L]

    const size_t smem_bytes = (size_t)SMEM_FLOATS * sizeof(float);  // ~202.8 KB
    cudaFuncSetAttribute(attn_fused_kernel,
                         cudaFuncAttributeMaxDynamicSharedMemorySize,
                         (int)smem_bytes);

    dim3 grid(Lv / BM, Bv);
    attn_fused_kernel<<<grid, NT, smem_bytes>>>(Q, C, M, out, att);
}

// round 8
// speedup vs baseline: 2.2547x; 1.1088x over previous
#include <cuda_runtime.h>
#include <math.h>

#define Bv 8
#define Lv 2048
#define Dv 64
#define BM 16            // query rows per CTA
#define BK 256           // k-tile
#define NTILE (Lv/BK)    // 8
#define NT 256           // 8 warps
#define NW 8
#define SCALE 0.125f     // 1/sqrt(64)
#define CTS 65           // C-tile row stride (floats): odd -> conflict-free both phases
#define QPS 10           // Qp row stride in ull (80B: keeps 16B alignment)

// smem floats: Ct 256*65=16640 + St 16*256=4096 + Qp 64*10*2=1280 + sums 128 + rinvs 16
#define SMEM_FLOATS (BK*CTS + BM*BK + Dv*QPS*2 + BM*NW + BM)

typedef unsigned long long ull;

#define FMA2(d_, a_, b_, c_) \
    asm("fma.rn.f32x2 %0, %1, %2, %3;" : "=l"(d_) : "l"(a_), "l"(b_), "l"(c_))
#define PACKF2(d_, x_, y_) \
    asm("mov.b64 %0, {%1, %2};" : "=l"(d_) : "f"(x_), "f"(y_))
#define UNPACKF2(x_, y_, s_) \
    asm("mov.b64 {%0, %1}, %2;" : "=f"(x_), "=f"(y_) : "l"(s_))

__global__ __launch_bounds__(NT, 2)
void attn_fused_kernel(const float* __restrict__ Q,
                       const float* __restrict__ C,
                       const unsigned char* __restrict__ M,
                       float* __restrict__ out,
                       float* __restrict__ att)
{
    extern __shared__ float smf[];
    float* Ct    = smf;                       // [BK][CTS]
    float* St    = Ct + BK*CTS;               // [BM][BK] e-tile
    ull*   Qp    = (ull*)(St + BM*BK);        // [Dv][QPS] row-pair packed Q
    float* sums  = (float*)(Qp + Dv*QPS);     // [BM][NW]
    float* rinvs = sums + BM*NW;              // [BM]

    const int t    = threadIdx.x;
    const int lane = t & 31;
    const int w    = t >> 5;                  // 0..7
    const int b    = blockIdx.y;
    const int q0   = blockIdx.x * BM;

    const float* Qg = Q + (size_t)(b*Lv + q0) * Dv;
    const float* Cg = C + (size_t)b * Lv * Dv;
    const unsigned char* Mg = M + (size_t)(b*Lv + q0) * Lv;
    float* attb = att + (size_t)(b*Lv + q0) * Lv;

    // ---- build Qp[d][rp] = pack(Q[2rp][d], Q[2rp+1][d]) ----
    #pragma unroll
    for (int i = t; i < Dv*8; i += NT) {
        const int d = i >> 3, rp = i & 7;
        ull v; PACKF2(v, Qg[(2*rp)*Dv + d], Qg[(2*rp+1)*Dv + d]);
        Qp[d*QPS + rp] = v;
    }

    float psum[16];
    #pragma unroll
    for (int r = 0; r < 16; ++r) psum[r] = 0.f;
    ull acc[8][2];
    #pragma unroll
    for (int rp = 0; rp < 8; ++rp) { acc[rp][0] = 0; acc[rp][1] = 0; }

    #pragma unroll 1
    for (int kt = 0; kt < NTILE; ++kt) {
        __syncthreads();   // prev ph2 done with Ct/St
        // ---- stage C tile: addr = idx + (idx>>6)  (== k*65 + d) ----
        const float* src = Cg + (size_t)kt*BK*Dv;
        #pragma unroll
        for (int hf = 0; hf < 4; ++hf) {
            float rr[16];
            #pragma unroll
            for (int j = 0; j < 16; ++j) rr[j] = src[t + NT*(hf*16 + j)];
            #pragma unroll
            for (int j = 0; j < 16; ++j) {
                const int idx = t + NT*(hf*16 + j);
                Ct[idx + (idx >> 6)] = rr[j];
            }
        }
        __syncthreads();   // staged

        // ---- ph1: warp w = col-seg (32 cols), all 16 rows ----
        ull a[8];
        #pragma unroll
        for (int rp = 0; rp < 8; ++rp) a[rp] = 0;
        const float* cp = Ct + (w*32 + lane)*CTS;
        #pragma unroll
        for (int d = 0; d < Dv; ++d) {
            const float c = cp[d];
            ull cc; PACKF2(cc, c, c);
            const ulonglong2 qA = *(const ulonglong2*)(Qp + d*QPS);
            const ulonglong2 qB = *(const ulonglong2*)(Qp + d*QPS + 2);
            const ulonglong2 qC = *(const ulonglong2*)(Qp + d*QPS + 4);
            const ulonglong2 qD = *(const ulonglong2*)(Qp + d*QPS + 6);
            FMA2(a[0], qA.x, cc, a[0]); FMA2(a[1], qA.y, cc, a[1]);
            FMA2(a[2], qB.x, cc, a[2]); FMA2(a[3], qB.y, cc, a[3]);
            FMA2(a[4], qC.x, cc, a[4]); FMA2(a[5], qC.y, cc, a[5]);
            FMA2(a[6], qD.x, cc, a[6]); FMA2(a[7], qD.y, cc, a[7]);
        }

        // ---- e epilogue: exp, psum, St smem, unnormalized att -> gmem ----
        const int k = kt*BK + w*32 + lane;
        #pragma unroll
        for (int rp = 0; rp < 8; ++rp) {
            float s0, s1; UNPACKF2(s0, s1, a[rp]);
            const int r0 = 2*rp, r1 = 2*rp + 1;
            float e0 = Mg[(size_t)r0*Lv + k] ? 0.f : __expf(s0 * SCALE);
            float e1 = Mg[(size_t)r1*Lv + k] ? 0.f : __expf(s1 * SCALE);
            psum[r0] += e0; psum[r1] += e1;
            St[r0*BK + w*32 + lane] = e0;
            St[r1*BK + w*32 + lane] = e1;
            attb[(size_t)r0*Lv + k] = e0;
            attb[(size_t)r1*Lv + k] = e1;
        }
        __syncthreads();   // St complete

        // ---- ph2: warp w = k-seg (32 k), 16 rows x cols (lane, lane+32) ----
        const float* c2p = Ct + (w*32)*CTS + lane;
        const float* s2p = St + w*32;
        #pragma unroll
        for (int kk = 0; kk < 8; ++kk) {
            ull cc0[4], cc1[4];
            #pragma unroll
            for (int q = 0; q < 4; ++q) {
                const float c0 = c2p[(kk*4 + q)*CTS];
                const float c1 = c2p[(kk*4 + q)*CTS + 32];
                PACKF2(cc0[q], c0, c0);
                PACKF2(cc1[q], c1, c1);
            }
            #pragma unroll
            for (int rq = 0; rq < 4; ++rq) {   // row quads: rows 4rq..4rq+3
                const float4 sv0 = *(const float4*)(s2p + (4*rq+0)*BK + kk*4);
                const float4 sv1 = *(const float4*)(s2p + (4*rq+1)*BK + kk*4);
                const float4 sv2 = *(const float4*)(s2p + (4*rq+2)*BK + kk*4);
                const float4 sv3 = *(const float4*)(s2p + (4*rq+3)*BK + kk*4);
                ull s2;
                #define PH2STEP(comp, ci) \
                    PACKF2(s2, sv0.comp, sv1.comp); \
                    FMA2(acc[2*rq][0],   s2, cc0[ci], acc[2*rq][0]); \
                    FMA2(acc[2*rq][1],   s2, cc1[ci], acc[2*rq][1]); \
                    PACKF2(s2, sv2.comp, sv3.comp); \
                    FMA2(acc[2*rq+1][0], s2, cc0[ci], acc[2*rq+1][0]); \
                    FMA2(acc[2*rq+1][1], s2, cc1[ci], acc[2*rq+1][1]);
                PH2STEP(x, 0)
                PH2STEP(y, 1)
                PH2STEP(z, 2)
                PH2STEP(w, 3)
                #undef PH2STEP
            }
        }
    }

    // ---- row-sum reduction -> rinvs ----
    #pragma unroll
    for (int r = 0; r < 16; ++r) {
        float v = psum[r];
        #pragma unroll
        for (int o = 16; o; o >>= 1) v += __shfl_xor_sync(0xffffffffu, v, o);
        if (lane == 0) sums[r*NW + w] = v;
    }
    __syncthreads();
    if (t < BM) {
        float s = 0.f;
        #pragma unroll
        for (int p = 0; p < NW; ++p) s += sums[t*NW + p];
        rinvs[t] = 1.0f / s;
    }
    __syncthreads();

    // ---- out: cross-warp (k-seg) reduction via smem (reuse Ct) ----
    float* Ored = Ct;   // 8*16*64 = 8192 floats
    #pragma unroll
    for (int rp = 0; rp < 8; ++rp) {
        float lo0, hi0, lo1, hi1;
        UNPACKF2(lo0, hi0, acc[rp][0]);   // col = lane
        UNPACKF2(lo1, hi1, acc[rp][1]);   // col = lane+32
        Ored[(w*16 + 2*rp)*64 + lane]        = lo0;
        Ored[(w*16 + 2*rp + 1)*64 + lane]    = hi0;
        Ored[(w*16 + 2*rp)*64 + lane + 32]     = lo1;
        Ored[(w*16 + 2*rp + 1)*64 + lane + 32] = hi1;
    }
    __syncthreads();
    #pragma unroll
    for (int i = 0; i < 4; ++i) {
        const int idx = t + NT*i;           // 0..1023
        const int row = idx >> 6, col = idx & 63;
        float v = 0.f;
        #pragma unroll
        for (int p = 0; p < NW; ++p) v += Ored[(p*16 + row)*64 + col];
        out[(size_t)(b*Lv + q0 + row)*Dv + col] = v * rinvs[row];
    }

    // ---- normalize att in place (CTA owns its 16 rows) ----
    #pragma unroll
    for (int i = 0; i < 32; ++i) {
        const int idx = t + NT*i;           // 0..8191 float4
        const int row = idx >> 9, c4 = idx & 511;
        float4* p = (float4*)(attb + (size_t)row*Lv) + c4;
        float4 v = *p;
        const float rv = rinvs[row];
        v.x *= rv; v.y *= rv; v.z *= rv; v.w *= rv;
        *p = v;
    }
}

extern "C" void kernel_launch(void* const* d_in, const int* in_sizes, int n_in,
                              void* d_out, int out_size) {
    const float* Q = (const float*)d_in[0];
    const float* C = (const float*)d_in[1];
    const unsigned char* M = (const unsigned char*)d_in[2];

    float* out = (float*)d_out;                   // [B, L, D]
    float* att = out + (size_t)Bv * Lv * Dv;      // [B, L, L]

    const size_t smem_bytes = (size_t)SMEM_FLOATS * sizeof(float);  // 88,640 B
    cudaFuncSetAttribute(attn_fused_kernel,
                         cudaFuncAttributeMaxDynamicSharedMemorySize,
                         (int)smem_bytes);

    dim3 grid(Lv / BM, Bv);
    attn_fused_kernel<<<grid, NT, smem_bytes>>>(Q, C, M, out, att);
}

// round 9
// speedup vs baseline: 2.4405x; 1.0824x over previous
#include <cuda_runtime.h>
#include <math.h>

#define Bv 8
#define Lv 2048
#define Dv 64
#define BM 16            // query rows per CTA
#define BK 256           // k-tile
#define NTILE (Lv/BK)    // 8
#define NT 256           // 8 warps
#define NW 8
#define SCALE 0.125f     // 1/sqrt(64)
#define CTS 65           // C-tile row stride (floats): odd -> conflict-free
#define STTS 20          // St_t row stride (floats): 5 float4-units (odd) -> conflict-free STS.128
#define QPS 10           // Qp row stride in ull (80B)

// smem floats: Ct 256*65=16640 + St_t 256*20=5120 + Qp 64*10*2=1280 + sums 128 + rinvs 16
#define SMEM_FLOATS (BK*CTS + BK*STTS + Dv*QPS*2 + BM*NW + BM)

typedef unsigned long long ull;

#define FMA2(d_, a_, b_, c_) \
    asm("fma.rn.f32x2 %0, %1, %2, %3;" : "=l"(d_) : "l"(a_), "l"(b_), "l"(c_))
#define PACKF2(d_, x_, y_) \
    asm("mov.b64 %0, {%1, %2};" : "=l"(d_) : "f"(x_), "f"(y_))
#define UNPACKF2(x_, y_, s_) \
    asm("mov.b64 {%0, %1}, %2;" : "=f"(x_), "=f"(y_) : "l"(s_))

__global__ __launch_bounds__(NT, 2)
void attn_fused_kernel(const float* __restrict__ Q,
                       const float* __restrict__ C,
                       const unsigned char* __restrict__ M,
                       float* __restrict__ out,
                       float* __restrict__ att)
{
    extern __shared__ float smf[];
    float* Ct    = smf;                       // [BK][CTS]  natural C tile
    float* St_t  = Ct + BK*CTS;               // [BK][STTS] transposed e-tile: St_t[k][row]
    ull*   Qp    = (ull*)(St_t + BK*STTS);    // [Dv][QPS]  row-pair packed Q
    float* sums  = (float*)(Qp + Dv*QPS);     // [BM][NW]
    float* rinvs = sums + BM*NW;              // [BM]

    const int t    = threadIdx.x;
    const int lane = t & 31;
    const int w    = t >> 5;                  // 0..7
    const int b    = blockIdx.y;
    const int q0   = blockIdx.x * BM;

    const float* Qg = Q + (size_t)(b*Lv + q0) * Dv;
    const float* Cg = C + (size_t)b * Lv * Dv;
    const unsigned char* Mg = M + (size_t)(b*Lv + q0) * Lv;
    float* attb = att + (size_t)(b*Lv + q0) * Lv;

    // ---- build Qp[d][rp] = pack(Q[2rp][d], Q[2rp+1][d]) ----
    #pragma unroll
    for (int i = t; i < Dv*8; i += NT) {
        const int d = i >> 3, rp = i & 7;
        ull v; PACKF2(v, Qg[(2*rp)*Dv + d], Qg[(2*rp+1)*Dv + d]);
        Qp[d*QPS + rp] = v;
    }

    float psum[16];
    #pragma unroll
    for (int r = 0; r < 16; ++r) psum[r] = 0.f;
    ull acc[8][2];
    #pragma unroll
    for (int rp = 0; rp < 8; ++rp) { acc[rp][0] = 0; acc[rp][1] = 0; }

    #pragma unroll 1
    for (int kt = 0; kt < NTILE; ++kt) {
        __syncthreads();   // prev ph2 done with Ct/St_t
        // ---- stage C tile: addr = idx + (idx>>6)  (== k*65 + d), conflict-free ----
        const float* src = Cg + (size_t)kt*BK*Dv;
        #pragma unroll
        for (int hf = 0; hf < 4; ++hf) {
            float rr[16];
            #pragma unroll
            for (int j = 0; j < 16; ++j) rr[j] = src[t + NT*(hf*16 + j)];
            #pragma unroll
            for (int j = 0; j < 16; ++j) {
                const int idx = t + NT*(hf*16 + j);
                Ct[idx + (idx >> 6)] = rr[j];
            }
        }
        __syncthreads();   // staged

        // ---- ph1: warp w = col-seg (32 cols), all 16 rows (packed pairs) ----
        ull a[8];
        #pragma unroll
        for (int rp = 0; rp < 8; ++rp) a[rp] = 0;
        const int kl = w*32 + lane;           // k within tile
        const float* cp = Ct + kl*CTS;
        #pragma unroll
        for (int d = 0; d < Dv; ++d) {
            const float c = cp[d];
            ull cc; PACKF2(cc, c, c);
            const ulonglong2 qA = *(const ulonglong2*)(Qp + d*QPS);
            const ulonglong2 qB = *(const ulonglong2*)(Qp + d*QPS + 2);
            const ulonglong2 qC = *(const ulonglong2*)(Qp + d*QPS + 4);
            const ulonglong2 qD = *(const ulonglong2*)(Qp + d*QPS + 6);
            FMA2(a[0], qA.x, cc, a[0]); FMA2(a[1], qA.y, cc, a[1]);
            FMA2(a[2], qB.x, cc, a[2]); FMA2(a[3], qB.y, cc, a[3]);
            FMA2(a[4], qC.x, cc, a[4]); FMA2(a[5], qC.y, cc, a[5]);
            FMA2(a[6], qD.x, cc, a[6]); FMA2(a[7], qD.y, cc, a[7]);
        }

        // ---- e epilogue: exp, psum, transposed St_t store, unnorm att -> gmem ----
        const int k = kt*BK + kl;
        float* stp = St_t + kl*STTS;
        #pragma unroll
        for (int q = 0; q < 4; ++q) {
            float s0, s1, s2, s3;
            UNPACKF2(s0, s1, a[2*q]);         // rows 4q, 4q+1
            UNPACKF2(s2, s3, a[2*q+1]);       // rows 4q+2, 4q+3
            const int r0 = 4*q;
            float e0 = Mg[(size_t)(r0+0)*Lv + k] ? 0.f : __expf(s0 * SCALE);
            float e1 = Mg[(size_t)(r0+1)*Lv + k] ? 0.f : __expf(s1 * SCALE);
            float e2 = Mg[(size_t)(r0+2)*Lv + k] ? 0.f : __expf(s2 * SCALE);
            float e3 = Mg[(size_t)(r0+3)*Lv + k] ? 0.f : __expf(s3 * SCALE);
            psum[r0+0] += e0; psum[r0+1] += e1;
            psum[r0+2] += e2; psum[r0+3] += e3;
            *(float4*)(stp + 4*q) = make_float4(e0, e1, e2, e3);  // conflict-free STS.128
            attb[(size_t)(r0+0)*Lv + k] = e0;
            attb[(size_t)(r0+1)*Lv + k] = e1;
            attb[(size_t)(r0+2)*Lv + k] = e2;
            attb[(size_t)(r0+3)*Lv + k] = e3;
        }
        __syncthreads();   // St_t complete

        // ---- ph2: warp w = k-seg (32 k), 16 rows x cols (lane, lane+32) ----
        // S pairs come PRE-PACKED from St_t (ulonglong2 = 2 row-pairs). Zero S packs.
        const float* c2p = Ct + (w*32)*CTS + lane;
        const float* s2p = St_t + (w*32)*STTS;
        #pragma unroll 4
        for (int kk = 0; kk < 32; ++kk) {
            const float c0 = c2p[kk*CTS];
            const float c1 = c2p[kk*CTS + 32];
            ull cc0, cc1;
            PACKF2(cc0, c0, c0);
            PACKF2(cc1, c1, c1);
            const ulonglong2 sA = *(const ulonglong2*)(s2p + kk*STTS);      // rp0, rp1
            const ulonglong2 sB = *(const ulonglong2*)(s2p + kk*STTS + 4);  // rp2, rp3
            const ulonglong2 sC = *(const ulonglong2*)(s2p + kk*STTS + 8);  // rp4, rp5
            const ulonglong2 sD = *(const ulonglong2*)(s2p + kk*STTS + 12); // rp6, rp7
            FMA2(acc[0][0], sA.x, cc0, acc[0][0]); FMA2(acc[0][1], sA.x, cc1, acc[0][1]);
            FMA2(acc[1][0], sA.y, cc0, acc[1][0]); FMA2(acc[1][1], sA.y, cc1, acc[1][1]);
            FMA2(acc[2][0], sB.x, cc0, acc[2][0]); FMA2(acc[2][1], sB.x, cc1, acc[2][1]);
            FMA2(acc[3][0], sB.y, cc0, acc[3][0]); FMA2(acc[3][1], sB.y, cc1, acc[3][1]);
            FMA2(acc[4][0], sC.x, cc0, acc[4][0]); FMA2(acc[4][1], sC.x, cc1, acc[4][1]);
            FMA2(acc[5][0], sC.y, cc0, acc[5][0]); FMA2(acc[5][1], sC.y, cc1, acc[5][1]);
            FMA2(acc[6][0], sD.x, cc0, acc[6][0]); FMA2(acc[6][1], sD.x, cc1, acc[6][1]);
            FMA2(acc[7][0], sD.y, cc0, acc[7][0]); FMA2(acc[7][1], sD.y, cc1, acc[7][1]);
        }
    }

    // ---- row-sum reduction -> rinvs ----
    #pragma unroll
    for (int r = 0; r < 16; ++r) {
        float v = psum[r];
        #pragma unroll
        for (int o = 16; o; o >>= 1) v += __shfl_xor_sync(0xffffffffu, v, o);
        if (lane == 0) sums[r*NW + w] = v;
    }
    __syncthreads();
    if (t < BM) {
        float s = 0.f;
        #pragma unroll
        for (int p = 0; p < NW; ++p) s += sums[t*NW + p];
        rinvs[t] = 1.0f / s;
    }
    __syncthreads();

    // ---- out: cross-warp (k-seg) reduction via smem (reuse Ct) ----
    float* Ored = Ct;   // 8*16*64 = 8192 floats
    #pragma unroll
    for (int rp = 0; rp < 8; ++rp) {
        float lo0, hi0, lo1, hi1;
        UNPACKF2(lo0, hi0, acc[rp][0]);   // col = lane
        UNPACKF2(lo1, hi1, acc[rp][1]);   // col = lane+32
        Ored[(w*16 + 2*rp)*64 + lane]          = lo0;
        Ored[(w*16 + 2*rp + 1)*64 + lane]      = hi0;
        Ored[(w*16 + 2*rp)*64 + lane + 32]     = lo1;
        Ored[(w*16 + 2*rp + 1)*64 + lane + 32] = hi1;
    }
    __syncthreads();
    #pragma unroll
    for (int i = 0; i < 4; ++i) {
        const int idx = t + NT*i;           // 0..1023
        const int row = idx >> 6, col = idx & 63;
        float v = 0.f;
        #pragma unroll
        for (int p = 0; p < NW; ++p) v += Ored[(p*16 + row)*64 + col];
        out[(size_t)(b*Lv + q0 + row)*Dv + col] = v * rinvs[row];
    }

    // ---- normalize att in place (CTA owns its 16 rows) ----
    #pragma unroll
    for (int i = 0; i < 32; ++i) {
        const int idx = t + NT*i;           // 0..8191 float4
        const int row = idx >> 9, c4 = idx & 511;
        float4* p = (float4*)(attb + (size_t)row*Lv) + c4;
        float4 v = *p;
        const float rv = rinvs[row];
        v.x *= rv; v.y *= rv; v.z *= rv; v.w *= rv;
        *p = v;
    }
}

extern "C" void kernel_launch(void* const* d_in, const int* in_sizes, int n_in,
                              void* d_out, int out_size) {
    const float* Q = (const float*)d_in[0];
    const float* C = (const float*)d_in[1];
    const unsigned char* M = (const unsigned char*)d_in[2];

    float* out = (float*)d_out;                   // [B, L, D]
    float* att = out + (size_t)Bv * Lv * Dv;      // [B, L, L]

    const size_t smem_bytes = (size_t)SMEM_FLOATS * sizeof(float);  // 92,736 B
    cudaFuncSetAttribute(attn_fused_kernel,
                         cudaFuncAttributeMaxDynamicSharedMemorySize,
                         (int)smem_bytes);

    dim3 grid(Lv / BM, Bv);
    attn_fused_kernel<<<grid, NT, smem_bytes>>>(Q, C, M, out, att);
}

// round 10
// speedup vs baseline: 2.5866x; 1.0599x over previous
#include <cuda_runtime.h>
#include <math.h>

#define Bv 8
#define Lv 2048
#define Dv 64
#define BM 32            // query rows per CTA
#define BK 256           // k-tile
#define NTILE (Lv/BK)    // 8
#define NT 256           // 8 warps
#define NW 8
#define SCALE 0.125f     // 1/sqrt(64)
#define CTS 65           // C-tile row stride (floats): conflict-free
#define STTS 36          // St_t row stride (floats): 9 float4-units (odd) -> conflict-free
#define QPSU 18          // Qp row stride in ull (144B, 16B-aligned)

// smem floats: Ct 256*65=16640 + St_t 256*36=9216 + Qp 64*18*2=2304 + sums 128 + rinvs 32
#define SMEM_FLOATS (BK*CTS + BK*STTS + Dv*QPSU*2 + BM*4 + BM)   // 28320 floats = 113,280 B

typedef unsigned long long ull;

#define FMA2(d_, a_, b_, c_) \
    asm("fma.rn.f32x2 %0, %1, %2, %3;" : "=l"(d_) : "l"(a_), "l"(b_), "l"(c_))
#define PACKF2(d_, x_, y_) \
    asm("mov.b64 %0, {%1, %2};" : "=l"(d_) : "f"(x_), "f"(y_))
#define UNPACKF2(x_, y_, s_) \
    asm("mov.b64 {%0, %1}, %2;" : "=f"(x_), "=f"(y_) : "l"(s_))

__global__ __launch_bounds__(NT, 2)
void attn_fused_kernel(const float* __restrict__ Q,
                       const float* __restrict__ C,
                       const unsigned char* __restrict__ M,
                       float* __restrict__ out,
                       float* __restrict__ att)
{
    extern __shared__ float smf[];
    float* Ct    = smf;                       // [BK][CTS]   C tile: Ct[k][d] at k*65+d
    float* St_t  = Ct + BK*CTS;               // [BK][STTS]  transposed e: St_t[k][row 0..31]
    ull*   Qp    = (ull*)(St_t + BK*STTS);    // [Dv][QPSU]  row-pair packed Q
    float* sums  = (float*)(Qp + Dv*QPSU);    // [BM][4]
    float* rinvs = sums + BM*4;               // [BM]

    const int t    = threadIdx.x;
    const int lane = t & 31;
    const int w    = t >> 5;                  // 0..7
    const int rh   = w >> 2;                  // row-half: rows rh*16 .. rh*16+15
    const int cq   = w & 3;                   // col/k quarter (64 wide)
    const int b    = blockIdx.y;
    const int q0   = blockIdx.x * BM;

    const float* Qg = Q + (size_t)(b*Lv + q0) * Dv;
    const float* Cg = C + (size_t)b * Lv * Dv;
    const unsigned char* Mg = M + (size_t)(b*Lv + q0) * Lv;
    float* attb = att + (size_t)(b*Lv + q0) * Lv;

    // ---- build Qp[d][rp] = pack(Q[2rp][d], Q[2rp+1][d]), rp 0..15 ----
    #pragma unroll
    for (int i = t; i < Dv*16; i += NT) {
        const int d = i >> 4, rp = i & 15;
        ull v; PACKF2(v, Qg[(2*rp)*Dv + d], Qg[(2*rp+1)*Dv + d]);
        Qp[d*QPSU + rp] = v;
    }

    float psum[16];                            // warp-local rows (rh*16 + r)
    #pragma unroll
    for (int r = 0; r < 16; ++r) psum[r] = 0.f;
    ull acc[8][2];                             // ph2: [rp][colblock]
    #pragma unroll
    for (int rp = 0; rp < 8; ++rp) { acc[rp][0] = 0; acc[rp][1] = 0; }

    #pragma unroll 1
    for (int kt = 0; kt < NTILE; ++kt) {
        __syncthreads();   // prev ph2 done with Ct/St_t
        // ---- stage C tile: addr = idx + (idx>>6) (== k*65 + d), conflict-free ----
        const float* src = Cg + (size_t)kt*BK*Dv;
        #pragma unroll
        for (int hf = 0; hf < 4; ++hf) {
            float rr[16];
            #pragma unroll
            for (int j = 0; j < 16; ++j) rr[j] = src[t + NT*(hf*16 + j)];
            #pragma unroll
            for (int j = 0; j < 16; ++j) {
                const int idx = t + NT*(hf*16 + j);
                Ct[idx + (idx >> 6)] = rr[j];
            }
        }
        __syncthreads();   // staged

        // ---- ph1: warp (rh, cq): rows rh*16..+15, cols cq*64..+63 ----
        ull a[2][8];       // [colblock][rp]
        #pragma unroll
        for (int rp = 0; rp < 8; ++rp) { a[0][rp] = 0; a[1][rp] = 0; }
        {
            const float* cp0 = Ct + (cq*64 + lane)*CTS;
            const float* cp1 = cp0 + 32*CTS;
            const ull* qb = Qp + rh*8;
            #pragma unroll
            for (int d = 0; d < Dv; ++d) {
                const float c0 = cp0[d];
                const float c1 = cp1[d];
                ull cc0, cc1;
                PACKF2(cc0, c0, c0);
                PACKF2(cc1, c1, c1);
                const ulonglong2 qA = *(const ulonglong2*)(qb + d*QPSU);
                const ulonglong2 qB = *(const ulonglong2*)(qb + d*QPSU + 2);
                const ulonglong2 qC = *(const ulonglong2*)(qb + d*QPSU + 4);
                const ulonglong2 qD = *(const ulonglong2*)(qb + d*QPSU + 6);
                FMA2(a[0][0], qA.x, cc0, a[0][0]); FMA2(a[1][0], qA.x, cc1, a[1][0]);
                FMA2(a[0][1], qA.y, cc0, a[0][1]); FMA2(a[1][1], qA.y, cc1, a[1][1]);
                FMA2(a[0][2], qB.x, cc0, a[0][2]); FMA2(a[1][2], qB.x, cc1, a[1][2]);
                FMA2(a[0][3], qB.y, cc0, a[0][3]); FMA2(a[1][3], qB.y, cc1, a[1][3]);
                FMA2(a[0][4], qC.x, cc0, a[0][4]); FMA2(a[1][4], qC.x, cc1, a[1][4]);
                FMA2(a[0][5], qC.y, cc0, a[0][5]); FMA2(a[1][5], qC.y, cc1, a[1][5]);
                FMA2(a[0][6], qD.x, cc0, a[0][6]); FMA2(a[1][6], qD.x, cc1, a[1][6]);
                FMA2(a[0][7], qD.y, cc0, a[0][7]); FMA2(a[1][7], qD.y, cc1, a[1][7]);
            }
        }

        // ---- epilogue: exp, psum, St_t transposed store, unnorm att -> gmem ----
        #pragma unroll
        for (int cb = 0; cb < 2; ++cb) {
            const int kl = cq*64 + cb*32 + lane;     // k within tile
            const int k  = kt*BK + kl;
            float* stp = St_t + kl*STTS + rh*16;
            #pragma unroll
            for (int q = 0; q < 4; ++q) {
                float s0, s1, s2, s3;
                UNPACKF2(s0, s1, a[cb][2*q]);
                UNPACKF2(s2, s3, a[cb][2*q+1]);
                const int r0 = 4*q;                  // warp-local row base
                const int gr = rh*16 + r0;           // CTA row base
                float e0 = Mg[(size_t)(gr+0)*Lv + k] ? 0.f : __expf(s0 * SCALE);
                float e1 = Mg[(size_t)(gr+1)*Lv + k] ? 0.f : __expf(s1 * SCALE);
                float e2 = Mg[(size_t)(gr+2)*Lv + k] ? 0.f : __expf(s2 * SCALE);
                float e3 = Mg[(size_t)(gr+3)*Lv + k] ? 0.f : __expf(s3 * SCALE);
                psum[r0+0] += e0; psum[r0+1] += e1;
                psum[r0+2] += e2; psum[r0+3] += e3;
                *(float4*)(stp + 4*q) = make_float4(e0, e1, e2, e3);
                attb[(size_t)(gr+0)*Lv + k] = e0;
                attb[(size_t)(gr+1)*Lv + k] = e1;
                attb[(size_t)(gr+2)*Lv + k] = e2;
                attb[(size_t)(gr+3)*Lv + k] = e3;
            }
        }
        __syncthreads();   // St_t complete

        // ---- ph2: warp (rh, kq=cq): rows rh*16..+15, all 64 cols, k-seg 64 ----
        {
            const float* c2p = Ct + (cq*64)*CTS + lane;
            const float* s2p = St_t + (cq*64)*STTS + rh*16;
            #pragma unroll 4
            for (int kk = 0; kk < 64; ++kk) {
                const float c0 = c2p[kk*CTS];
                const float c1 = c2p[kk*CTS + 32];
                ull cc0, cc1;
                PACKF2(cc0, c0, c0);
                PACKF2(cc1, c1, c1);
                const ulonglong2 sA = *(const ulonglong2*)(s2p + kk*STTS);
                const ulonglong2 sB = *(const ulonglong2*)(s2p + kk*STTS + 4);
                const ulonglong2 sC = *(const ulonglong2*)(s2p + kk*STTS + 8);
                const ulonglong2 sD = *(const ulonglong2*)(s2p + kk*STTS + 12);
                FMA2(acc[0][0], sA.x, cc0, acc[0][0]); FMA2(acc[0][1], sA.x, cc1, acc[0][1]);
                FMA2(acc[1][0], sA.y, cc0, acc[1][0]); FMA2(acc[1][1], sA.y, cc1, acc[1][1]);
                FMA2(acc[2][0], sB.x, cc0, acc[2][0]); FMA2(acc[2][1], sB.x, cc1, acc[2][1]);
                FMA2(acc[3][0], sB.y, cc0, acc[3][0]); FMA2(acc[3][1], sB.y, cc1, acc[3][1]);
                FMA2(acc[4][0], sC.x, cc0, acc[4][0]); FMA2(acc[4][1], sC.x, cc1, acc[4][1]);
                FMA2(acc[5][0], sC.y, cc0, acc[5][0]); FMA2(acc[5][1], sC.y, cc1, acc[5][1]);
                FMA2(acc[6][0], sD.x, cc0, acc[6][0]); FMA2(acc[6][1], sD.x, cc1, acc[6][1]);
                FMA2(acc[7][0], sD.y, cc0, acc[7][0]); FMA2(acc[7][1], sD.y, cc1, acc[7][1]);
            }
        }
    }

    // ---- row-sum reduction -> rinvs (4 cq-partials per row) ----
    #pragma unroll
    for (int r = 0; r < 16; ++r) {
        float v = psum[r];
        #pragma unroll
        for (int o = 16; o; o >>= 1) v += __shfl_xor_sync(0xffffffffu, v, o);
        if (lane == 0) sums[(rh*16 + r)*4 + cq] = v;
    }
    __syncthreads();
    if (t < BM) {
        float s = (sums[t*4+0] + sums[t*4+1]) + (sums[t*4+2] + sums[t*4+3]);
        rinvs[t] = 1.0f / s;
    }
    __syncthreads();

    // ---- out: cross-warp (kq) reduction via smem (reuse Ct) ----
    float* Ored = Ct;   // 4*32*64 = 8192 floats
    #pragma unroll
    for (int rp = 0; rp < 8; ++rp) {
        float lo0, hi0, lo1, hi1;
        UNPACKF2(lo0, hi0, acc[rp][0]);   // col = lane
        UNPACKF2(lo1, hi1, acc[rp][1]);   // col = lane+32
        const int gr = rh*16 + 2*rp;
        Ored[(cq*32 + gr)*64 + lane]          = lo0;
        Ored[(cq*32 + gr + 1)*64 + lane]      = hi0;
        Ored[(cq*32 + gr)*64 + lane + 32]     = lo1;
        Ored[(cq*32 + gr + 1)*64 + lane + 32] = hi1;
    }
    __syncthreads();
    #pragma unroll
    for (int i = 0; i < 8; ++i) {
        const int idx = t + NT*i;           // 0..2047
        const int row = idx >> 6, col = idx & 63;
        float v = (Ored[(0*32 + row)*64 + col] + Ored[(1*32 + row)*64 + col])
                + (Ored[(2*32 + row)*64 + col] + Ored[(3*32 + row)*64 + col]);
        out[(size_t)(b*Lv + q0 + row)*Dv + col] = v * rinvs[row];
    }

    // ---- normalize att in place (CTA owns its 32 rows) ----
    #pragma unroll
    for (int i = 0; i < 64; ++i) {
        const int idx = t + NT*i;           // 0..16383 float4
        const int row = idx >> 9, c4 = idx & 511;
        float4* p = (float4*)(attb + (size_t)row*Lv) + c4;
        float4 v = *p;
        const float rv = rinvs[row];
        v.x *= rv; v.y *= rv; v.z *= rv; v.w *= rv;
        *p = v;
    }
}

extern "C" void kernel_launch(void* const* d_in, const int* in_sizes, int n_in,
                              void* d_out, int out_size) {
    const float* Q = (const float*)d_in[0];
    const float* C = (const float*)d_in[1];
    const unsigned char* M = (const unsigned char*)d_in[2];

    float* out = (float*)d_out;                   // [B, L, D]
    float* att = out + (size_t)Bv * Lv * Dv;      // [B, L, L]

    const size_t smem_bytes = (size_t)SMEM_FLOATS * sizeof(float);  // 113,280 B
    cudaFuncSetAttribute(attn_fused_kernel,
                         cudaFuncAttributeMaxDynamicSharedMemorySize,
                         (int)smem_bytes);

    dim3 grid(Lv / BM, Bv);
    attn_fused_kernel<<<grid, NT, smem_bytes>>>(Q, C, M, out, att);
}